// round 4
// baseline (speedup 1.0000x reference)
#include <cuda_runtime.h>
#include <math.h>

#define Bq    2
#define Tq    2048
#define BT    4096
#define Dq    512
#define Sq    256
#define Lq    4
#define DFFq  1368
#define Vq    32000
#define EPSq  1e-5f
#define NCHUNK 16
#define CLEN   128   // Tq / NCHUNK

// ---------------- scratch (no cudaMalloc allowed) ----------------
__device__ __align__(128) float g_h [(size_t)BT * Dq];    // residual stream
__device__ __align__(128) float g_ln[(size_t)BT * Dq];    // LN output
__device__ __align__(128) float g_bu[(size_t)BT * Sq];    // Bu, then scanned h
__device__ __align__(128) float g_carry[Bq * Sq * NCHUNK];
__device__ __align__(128) float g_ff[(size_t)BT * DFFq];  // gate, then gated prod

// ---------------- embedding: h = emb[x] + pos[t] ----------------
__global__ void k_embed(const int* __restrict__ x, const float* __restrict__ emb,
                        const float* __restrict__ pos)
{
    const int row = blockIdx.x;          // 0..4095 = b*2048 + t
    const int t   = row & (Tq - 1);
    const int tok = x[row];
    const float4* e = (const float4*)(emb + (size_t)tok * Dq);
    const float4* p = (const float4*)(pos + (size_t)t * Dq);
    float4* o = (float4*)(g_h + (size_t)row * Dq);
    const int c = threadIdx.x;           // 128 threads, 4 floats each
    float4 a = e[c], b = p[c];
    o[c] = make_float4(a.x + b.x, a.y + b.y, a.z + b.z, a.w + b.w);
}

// ---------------- layernorm (one block per token row) ----------------
__global__ void k_ln(const float* __restrict__ in, float* __restrict__ out,
                     const float* __restrict__ w, const float* __restrict__ b)
{
    const int row = blockIdx.x;
    const int c = threadIdx.x;           // 0..127
    const float4 v = ((const float4*)(in + (size_t)row * Dq))[c];
    float s  = v.x + v.y + v.z + v.w;
    float ss = v.x*v.x + v.y*v.y + v.z*v.z + v.w*v.w;
#pragma unroll
    for (int o = 16; o > 0; o >>= 1) {
        s  += __shfl_xor_sync(0xffffffffu, s,  o);
        ss += __shfl_xor_sync(0xffffffffu, ss, o);
    }
    __shared__ float sm[10];
    const int wid = c >> 5;
    if ((c & 31) == 0) { sm[wid] = s; sm[4 + wid] = ss; }
    __syncthreads();
    if (c == 0) {
        float S1 = sm[0] + sm[1] + sm[2] + sm[3];
        float S2 = sm[4] + sm[5] + sm[6] + sm[7];
        float mu  = S1 * (1.0f / Dq);
        float var = S2 * (1.0f / Dq) - mu * mu;
        sm[8] = mu;
        sm[9] = rsqrtf(var + EPSq);
    }
    __syncthreads();
    const float mu = sm[8], rs = sm[9];
    const float4 wv = ((const float4*)w)[c];
    const float4 bv = ((const float4*)b)[c];
    float4 o;
    o.x = (v.x - mu) * rs * wv.x + bv.x;
    o.y = (v.y - mu) * rs * wv.y + bv.y;
    o.z = (v.z - mu) * rs * wv.z + bv.z;
    o.w = (v.w - mu) * rs * wv.w + bv.w;
    ((float4*)(out + (size_t)row * Dq))[c] = o;
}

// ---------------- SGEMM: C = A[M,K] * B[N,K]^T, fused epilogues ----------------
// MODE 0: C = acc
// MODE 1: C = silu(C) * acc                       (SwiGLU second GEMM)
// MODE 2: C = C + acc + aux1[n] * aux2[m,n]       (SSM residual: Dp*u)
// MODE 3: C = C + acc                             (FFN residual)
// MODE 4: C = acc + aux1[n]                       (head bias)
template<int MODE>
__global__ void __launch_bounds__(256, 2)
k_gemm(const float* __restrict__ A, const float* __restrict__ B,
       float* __restrict__ C, int M, int N, int K,
       const float* __restrict__ aux1, const float* __restrict__ aux2)
{
    __shared__ float As[8][128];
    __shared__ float Bs[8][128];
    const int bm = blockIdx.y * 128;
    const int bn = blockIdx.x * 128;
    const int tid = threadIdx.x;
    const int tx = tid & 15;
    const int ty = tid >> 4;
    const int lrow = tid >> 1;           // 0..127
    const int lcol = (tid & 1) * 4;      // 0 or 4

    float acc[8][8];
#pragma unroll
    for (int i = 0; i < 8; i++)
#pragma unroll
        for (int j = 0; j < 8; j++) acc[i][j] = 0.f;

    const float* Aptr = A + (size_t)(bm + lrow) * K + lcol;
    const float* Bptr = B + (size_t)(bn + lrow) * K + lcol;
    const bool bvalid = (bn + lrow) < N;

    for (int k0 = 0; k0 < K; k0 += 8) {
        float4 av = *(const float4*)(Aptr + k0);
        float4 bv = make_float4(0.f, 0.f, 0.f, 0.f);
        if (bvalid) bv = *(const float4*)(Bptr + k0);
        __syncthreads();
        As[lcol + 0][lrow] = av.x;
        As[lcol + 1][lrow] = av.y;
        As[lcol + 2][lrow] = av.z;
        As[lcol + 3][lrow] = av.w;
        Bs[lcol + 0][lrow] = bv.x;
        Bs[lcol + 1][lrow] = bv.y;
        Bs[lcol + 2][lrow] = bv.z;
        Bs[lcol + 3][lrow] = bv.w;
        __syncthreads();
#pragma unroll
        for (int k = 0; k < 8; k++) {
            float a[8], b[8];
            *(float4*)(a)     = *(const float4*)(&As[k][ty * 8]);
            *(float4*)(a + 4) = *(const float4*)(&As[k][ty * 8 + 4]);
            *(float4*)(b)     = *(const float4*)(&Bs[k][tx * 8]);
            *(float4*)(b + 4) = *(const float4*)(&Bs[k][tx * 8 + 4]);
#pragma unroll
            for (int i = 0; i < 8; i++)
#pragma unroll
                for (int j = 0; j < 8; j++)
                    acc[i][j] = fmaf(a[i], b[j], acc[i][j]);
        }
    }

#pragma unroll
    for (int i = 0; i < 8; i++) {
        const int m = bm + ty * 8 + i;
        const size_t rowoff = (size_t)m * N;
#pragma unroll
        for (int jj = 0; jj < 2; jj++) {
            const int n = bn + tx * 8 + jj * 4;
            if (n >= N) continue;       // N is always a multiple of 4
            float4 r;
            r.x = acc[i][jj*4+0]; r.y = acc[i][jj*4+1];
            r.z = acc[i][jj*4+2]; r.w = acc[i][jj*4+3];
            float4* cp = (float4*)(C + rowoff + n);
            if (MODE == 0) {
                *cp = r;
            } else if (MODE == 1) {
                float4 g = *cp;
                r.x *= g.x / (1.f + __expf(-g.x));
                r.y *= g.y / (1.f + __expf(-g.y));
                r.z *= g.z / (1.f + __expf(-g.z));
                r.w *= g.w / (1.f + __expf(-g.w));
                *cp = r;
            } else if (MODE == 2) {
                float4 c  = *cp;
                float4 dp = *(const float4*)(aux1 + n);
                float4 u  = *(const float4*)(aux2 + rowoff + n);
                r.x += c.x + dp.x * u.x;
                r.y += c.y + dp.y * u.y;
                r.z += c.z + dp.z * u.z;
                r.w += c.w + dp.w * u.w;
                *cp = r;
            } else if (MODE == 3) {
                float4 c = *cp;
                r.x += c.x; r.y += c.y; r.z += c.z; r.w += c.w;
                *cp = r;
            } else {
                float4 bb = *(const float4*)(aux1 + n);
                r.x += bb.x; r.y += bb.y; r.z += bb.z; r.w += bb.w;
                *cp = r;
            }
        }
    }
}

// ---------------- SSM scan: h[t] = lam*h[t-1] + Bu[t], chunked ----------------
// Phase 1: local scan per (b, s, chunk), zero initial state; record carry.
__global__ void k_scan1(const float* __restrict__ loglam)
{
    const int idx   = blockIdx.x * blockDim.x + threadIdx.x;  // 0..8191
    const int s     = idx & (Sq - 1);
    const int b     = (idx >> 8) & 1;
    const int chunk = idx >> 9;
    const float lam = 1.f / (1.f + expf(-loglam[s]));
    float* p = g_bu + ((size_t)(b * Tq + chunk * CLEN)) * Sq + s;
    float h = 0.f;
    float buf[4];
#pragma unroll
    for (int j = 0; j < 4; j++) buf[j] = p[(size_t)j * Sq];
    for (int j0 = 0; j0 < CLEN; j0 += 4) {
        float c0 = buf[0], c1 = buf[1], c2 = buf[2], c3 = buf[3];
        if (j0 + 4 < CLEN) {
#pragma unroll
            for (int j = 0; j < 4; j++) buf[j] = p[(size_t)(j0 + 4 + j) * Sq];
        }
        h = fmaf(lam, h, c0); p[(size_t)(j0 + 0) * Sq] = h;
        h = fmaf(lam, h, c1); p[(size_t)(j0 + 1) * Sq] = h;
        h = fmaf(lam, h, c2); p[(size_t)(j0 + 2) * Sq] = h;
        h = fmaf(lam, h, c3); p[(size_t)(j0 + 3) * Sq] = h;
    }
    g_carry[((size_t)b * Sq + s) * NCHUNK + chunk] = h;
}

// Phase 2: prefix over chunk carries -> incoming state H per chunk (in place).
__global__ void k_scan2(const float* __restrict__ loglam)
{
    const int idx = blockIdx.x * blockDim.x + threadIdx.x;    // 0..511
    const int s = idx & (Sq - 1);
    const int b = idx >> 8;
    const float lam = 1.f / (1.f + expf(-loglam[s]));
    float lp = lam;
#pragma unroll
    for (int i = 0; i < 7; i++) lp *= lp;                     // lam^128
    float* cb = g_carry + ((size_t)b * Sq + s) * NCHUNK;
    float H = 0.f;
#pragma unroll
    for (int c = 0; c < NCHUNK; c++) {
        float carry = cb[c];
        cb[c] = H;                                            // incoming state
        H = fmaf(lp, H, carry);
    }
}

// Phase 3: h_full[j] = h_local[j] + lam^{j+1} * H_in
__global__ void k_scan3(const float* __restrict__ loglam)
{
    const int idx   = blockIdx.x * blockDim.x + threadIdx.x;
    const int s     = idx & (Sq - 1);
    const int b     = (idx >> 8) & 1;
    const int chunk = idx >> 9;
    if (chunk == 0) return;                                   // H = 0
    const float lam = 1.f / (1.f + expf(-loglam[s]));
    const float H = g_carry[((size_t)b * Sq + s) * NCHUNK + chunk];
    float* p = g_bu + ((size_t)(b * Tq + chunk * CLEN)) * Sq + s;
    float f = lam;
    for (int j0 = 0; j0 < CLEN; j0 += 8) {
        float v[8];
#pragma unroll
        for (int u = 0; u < 8; u++) v[u] = p[(size_t)(j0 + u) * Sq];
#pragma unroll
        for (int u = 0; u < 8; u++) { v[u] += f * H; f *= lam; }
#pragma unroll
        for (int u = 0; u < 8; u++) p[(size_t)(j0 + u) * Sq] = v[u];
    }
}

// ---------------- orchestration ----------------
extern "C" void kernel_launch(void* const* d_in, const int* in_sizes, int n_in,
                              void* d_out, int out_size)
{
    const int*   x      = (const int*)  d_in[0];
    const float* emb    = (const float*)d_in[1];
    const float* pos    = (const float*)d_in[2];
    const float* loglam = (const float*)d_in[3];
    const float* Bw     = (const float*)d_in[4];
    const float* Cw     = (const float*)d_in[5];
    const float* Dp     = (const float*)d_in[6];
    const float* n1w    = (const float*)d_in[7];
    const float* n1b    = (const float*)d_in[8];
    const float* n2w    = (const float*)d_in[9];
    const float* n2b    = (const float*)d_in[10];
    const float* w1     = (const float*)d_in[11];
    const float* w2     = (const float*)d_in[12];
    const float* w3     = (const float*)d_in[13];
    const float* now    = (const float*)d_in[14];
    const float* nob    = (const float*)d_in[15];
    const float* headW  = (const float*)d_in[16];
    const float* headb  = (const float*)d_in[17];
    float* out = (float*)d_out;

    void *ph, *pl, *pb, *pf;
    cudaGetSymbolAddress(&ph, g_h);
    cudaGetSymbolAddress(&pl, g_ln);
    cudaGetSymbolAddress(&pb, g_bu);
    cudaGetSymbolAddress(&pf, g_ff);
    float* h  = (float*)ph;
    float* ln = (float*)pl;
    float* bu = (float*)pb;
    float* ff = (float*)pf;

    k_embed<<<BT, 128>>>(x, emb, pos);

    for (int l = 0; l < Lq; l++) {
        // ---- SSM block ----
        k_ln<<<BT, 128>>>(h, ln, n1w + l * Dq, n1b + l * Dq);
        k_gemm<0><<<dim3(Sq / 128, BT / 128), 256>>>(
            ln, Bw + (size_t)l * Sq * Dq, bu, BT, Sq, Dq, nullptr, nullptr);
        k_scan1<<<32, 256>>>(loglam + l * Sq);
        k_scan2<<<2, 256>>>(loglam + l * Sq);
        k_scan3<<<32, 256>>>(loglam + l * Sq);
        k_gemm<2><<<dim3(Dq / 128, BT / 128), 256>>>(
            bu, Cw + (size_t)l * Dq * Sq, h, BT, Dq, Sq, Dp + l * Dq, ln);
        // ---- SwiGLU block ----
        k_ln<<<BT, 128>>>(h, ln, n2w + l * Dq, n2b + l * Dq);
        k_gemm<0><<<dim3((DFFq + 127) / 128, BT / 128), 256>>>(
            ln, w1 + (size_t)l * DFFq * Dq, ff, BT, DFFq, Dq, nullptr, nullptr);
        k_gemm<1><<<dim3((DFFq + 127) / 128, BT / 128), 256>>>(
            ln, w2 + (size_t)l * DFFq * Dq, ff, BT, DFFq, Dq, nullptr, nullptr);
        k_gemm<3><<<dim3(Dq / 128, BT / 128), 256>>>(
            ff, w3 + (size_t)l * Dq * DFFq, h, BT, Dq, DFFq, nullptr, nullptr);
    }

    // ---- head ----
    k_ln<<<BT, 128>>>(h, ln, now, nob);
    k_gemm<4><<<dim3(Vq / 128, BT / 128), 256>>>(
        ln, headW, out, BT, Vq, Dq, headb, nullptr);
}

// round 5
// speedup vs baseline: 1.0001x; 1.0001x over previous
#include <cuda_runtime.h>
#include <math.h>

#define Bq    2
#define Tq    2048
#define BT    4096
#define Dq    512
#define Sq    256
#define Lq    4
#define DFFq  1368
#define Vq    32000
#define EPSq  1e-5f
#define NCHUNK 16
#define CLEN   128   // Tq / NCHUNK

// ---------------- scratch (no cudaMalloc allowed) ----------------
__device__ __align__(128) float g_h [(size_t)BT * Dq];    // residual stream
__device__ __align__(128) float g_ln[(size_t)BT * Dq];    // LN output
__device__ __align__(128) float g_bu[(size_t)BT * Sq];    // Bu, then scanned h
__device__ __align__(128) float g_carry[Bq * Sq * NCHUNK];
__device__ __align__(128) float g_ff[(size_t)BT * DFFq];  // gate, then gated prod

// ---------------- embedding: h = emb[x] + pos[t] ----------------
__global__ void k_embed(const int* __restrict__ x, const float* __restrict__ emb,
                        const float* __restrict__ pos)
{
    const int row = blockIdx.x;          // 0..4095 = b*2048 + t
    const int t   = row & (Tq - 1);
    const int tok = x[row];
    const float4* e = (const float4*)(emb + (size_t)tok * Dq);
    const float4* p = (const float4*)(pos + (size_t)t * Dq);
    float4* o = (float4*)(g_h + (size_t)row * Dq);
    const int c = threadIdx.x;           // 128 threads, 4 floats each
    float4 a = e[c], b = p[c];
    o[c] = make_float4(a.x + b.x, a.y + b.y, a.z + b.z, a.w + b.w);
}

// ---------------- layernorm (one block per token row) ----------------
__global__ void k_ln(const float* __restrict__ in, float* __restrict__ out,
                     const float* __restrict__ w, const float* __restrict__ b)
{
    const int row = blockIdx.x;
    const int c = threadIdx.x;           // 0..127
    const float4 v = ((const float4*)(in + (size_t)row * Dq))[c];
    float s  = v.x + v.y + v.z + v.w;
    float ss = v.x*v.x + v.y*v.y + v.z*v.z + v.w*v.w;
#pragma unroll
    for (int o = 16; o > 0; o >>= 1) {
        s  += __shfl_xor_sync(0xffffffffu, s,  o);
        ss += __shfl_xor_sync(0xffffffffu, ss, o);
    }
    __shared__ float sm[10];
    const int wid = c >> 5;
    if ((c & 31) == 0) { sm[wid] = s; sm[4 + wid] = ss; }
    __syncthreads();
    if (c == 0) {
        float S1 = sm[0] + sm[1] + sm[2] + sm[3];
        float S2 = sm[4] + sm[5] + sm[6] + sm[7];
        float mu  = S1 * (1.0f / Dq);
        float var = S2 * (1.0f / Dq) - mu * mu;
        sm[8] = mu;
        sm[9] = rsqrtf(var + EPSq);
    }
    __syncthreads();
    const float mu = sm[8], rs = sm[9];
    const float4 wv = ((const float4*)w)[c];
    const float4 bv = ((const float4*)b)[c];
    float4 o;
    o.x = (v.x - mu) * rs * wv.x + bv.x;
    o.y = (v.y - mu) * rs * wv.y + bv.y;
    o.z = (v.z - mu) * rs * wv.z + bv.z;
    o.w = (v.w - mu) * rs * wv.w + bv.w;
    ((float4*)(out + (size_t)row * Dq))[c] = o;
}

// ---------------- SGEMM: C = A[M,K] * B[N,K]^T, fused epilogues ----------------
// MODE 0: C = acc
// MODE 1: C = silu(C) * acc                       (SwiGLU second GEMM)
// MODE 2: C = C + acc + aux1[n] * aux2[m,n]       (SSM residual: Dp*u)
// MODE 3: C = C + acc                             (FFN residual)
// MODE 4: C = acc + aux1[n]                       (head bias)
template<int MODE>
__global__ void __launch_bounds__(256, 2)
k_gemm(const float* __restrict__ A, const float* __restrict__ B,
       float* __restrict__ C, int M, int N, int K,
       const float* __restrict__ aux1, const float* __restrict__ aux2)
{
    __shared__ float As[8][128];
    __shared__ float Bs[8][128];
    const int bm = blockIdx.y * 128;
    const int bn = blockIdx.x * 128;
    const int tid = threadIdx.x;
    const int tx = tid & 15;
    const int ty = tid >> 4;
    const int lrow = tid >> 1;           // 0..127
    const int lcol = (tid & 1) * 4;      // 0 or 4

    float acc[8][8];
#pragma unroll
    for (int i = 0; i < 8; i++)
#pragma unroll
        for (int j = 0; j < 8; j++) acc[i][j] = 0.f;

    const float* Aptr = A + (size_t)(bm + lrow) * K + lcol;
    const float* Bptr = B + (size_t)(bn + lrow) * K + lcol;
    const bool bvalid = (bn + lrow) < N;

    for (int k0 = 0; k0 < K; k0 += 8) {
        float4 av = *(const float4*)(Aptr + k0);
        float4 bv = make_float4(0.f, 0.f, 0.f, 0.f);
        if (bvalid) bv = *(const float4*)(Bptr + k0);
        __syncthreads();
        As[lcol + 0][lrow] = av.x;
        As[lcol + 1][lrow] = av.y;
        As[lcol + 2][lrow] = av.z;
        As[lcol + 3][lrow] = av.w;
        Bs[lcol + 0][lrow] = bv.x;
        Bs[lcol + 1][lrow] = bv.y;
        Bs[lcol + 2][lrow] = bv.z;
        Bs[lcol + 3][lrow] = bv.w;
        __syncthreads();
#pragma unroll
        for (int k = 0; k < 8; k++) {
            float a[8], b[8];
            *(float4*)(a)     = *(const float4*)(&As[k][ty * 8]);
            *(float4*)(a + 4) = *(const float4*)(&As[k][ty * 8 + 4]);
            *(float4*)(b)     = *(const float4*)(&Bs[k][tx * 8]);
            *(float4*)(b + 4) = *(const float4*)(&Bs[k][tx * 8 + 4]);
#pragma unroll
            for (int i = 0; i < 8; i++)
#pragma unroll
                for (int j = 0; j < 8; j++)
                    acc[i][j] = fmaf(a[i], b[j], acc[i][j]);
        }
    }

#pragma unroll
    for (int i = 0; i < 8; i++) {
        const int m = bm + ty * 8 + i;
        const size_t rowoff = (size_t)m * N;
#pragma unroll
        for (int jj = 0; jj < 2; jj++) {
            const int n = bn + tx * 8 + jj * 4;
            if (n >= N) continue;       // N is always a multiple of 4
            float4 r;
            r.x = acc[i][jj*4+0]; r.y = acc[i][jj*4+1];
            r.z = acc[i][jj*4+2]; r.w = acc[i][jj*4+3];
            float4* cp = (float4*)(C + rowoff + n);
            if (MODE == 0) {
                *cp = r;
            } else if (MODE == 1) {
                float4 g = *cp;
                r.x *= g.x / (1.f + __expf(-g.x));
                r.y *= g.y / (1.f + __expf(-g.y));
                r.z *= g.z / (1.f + __expf(-g.z));
                r.w *= g.w / (1.f + __expf(-g.w));
                *cp = r;
            } else if (MODE == 2) {
                float4 c  = *cp;
                float4 dp = *(const float4*)(aux1 + n);
                float4 u  = *(const float4*)(aux2 + rowoff + n);
                r.x += c.x + dp.x * u.x;
                r.y += c.y + dp.y * u.y;
                r.z += c.z + dp.z * u.z;
                r.w += c.w + dp.w * u.w;
                *cp = r;
            } else if (MODE == 3) {
                float4 c = *cp;
                r.x += c.x; r.y += c.y; r.z += c.z; r.w += c.w;
                *cp = r;
            } else {
                float4 bb = *(const float4*)(aux1 + n);
                r.x += bb.x; r.y += bb.y; r.z += bb.z; r.w += bb.w;
                *cp = r;
            }
        }
    }
}

// ---------------- SSM scan: h[t] = lam*h[t-1] + Bu[t], chunked ----------------
// Phase 1: local scan per (b, s, chunk), zero initial state; record carry.
__global__ void k_scan1(const float* __restrict__ loglam)
{
    const int idx   = blockIdx.x * blockDim.x + threadIdx.x;  // 0..8191
    const int s     = idx & (Sq - 1);
    const int b     = (idx >> 8) & 1;
    const int chunk = idx >> 9;
    const float lam = 1.f / (1.f + expf(-loglam[s]));
    float* p = g_bu + ((size_t)(b * Tq + chunk * CLEN)) * Sq + s;
    float h = 0.f;
    float buf[4];
#pragma unroll
    for (int j = 0; j < 4; j++) buf[j] = p[(size_t)j * Sq];
    for (int j0 = 0; j0 < CLEN; j0 += 4) {
        float c0 = buf[0], c1 = buf[1], c2 = buf[2], c3 = buf[3];
        if (j0 + 4 < CLEN) {
#pragma unroll
            for (int j = 0; j < 4; j++) buf[j] = p[(size_t)(j0 + 4 + j) * Sq];
        }
        h = fmaf(lam, h, c0); p[(size_t)(j0 + 0) * Sq] = h;
        h = fmaf(lam, h, c1); p[(size_t)(j0 + 1) * Sq] = h;
        h = fmaf(lam, h, c2); p[(size_t)(j0 + 2) * Sq] = h;
        h = fmaf(lam, h, c3); p[(size_t)(j0 + 3) * Sq] = h;
    }
    g_carry[((size_t)b * Sq + s) * NCHUNK + chunk] = h;
}

// Phase 2: prefix over chunk carries -> incoming state H per chunk (in place).
__global__ void k_scan2(const float* __restrict__ loglam)
{
    const int idx = blockIdx.x * blockDim.x + threadIdx.x;    // 0..511
    const int s = idx & (Sq - 1);
    const int b = idx >> 8;
    const float lam = 1.f / (1.f + expf(-loglam[s]));
    float lp = lam;
#pragma unroll
    for (int i = 0; i < 7; i++) lp *= lp;                     // lam^128
    float* cb = g_carry + ((size_t)b * Sq + s) * NCHUNK;
    float H = 0.f;
#pragma unroll
    for (int c = 0; c < NCHUNK; c++) {
        float carry = cb[c];
        cb[c] = H;                                            // incoming state
        H = fmaf(lp, H, carry);
    }
}

// Phase 3: h_full[j] = h_local[j] + lam^{j+1} * H_in
__global__ void k_scan3(const float* __restrict__ loglam)
{
    const int idx   = blockIdx.x * blockDim.x + threadIdx.x;
    const int s     = idx & (Sq - 1);
    const int b     = (idx >> 8) & 1;
    const int chunk = idx >> 9;
    if (chunk == 0) return;                                   // H = 0
    const float lam = 1.f / (1.f + expf(-loglam[s]));
    const float H = g_carry[((size_t)b * Sq + s) * NCHUNK + chunk];
    float* p = g_bu + ((size_t)(b * Tq + chunk * CLEN)) * Sq + s;
    float f = lam;
    for (int j0 = 0; j0 < CLEN; j0 += 8) {
        float v[8];
#pragma unroll
        for (int u = 0; u < 8; u++) v[u] = p[(size_t)(j0 + u) * Sq];
#pragma unroll
        for (int u = 0; u < 8; u++) { v[u] += f * H; f *= lam; }
#pragma unroll
        for (int u = 0; u < 8; u++) p[(size_t)(j0 + u) * Sq] = v[u];
    }
}

// ---------------- orchestration ----------------
extern "C" void kernel_launch(void* const* d_in, const int* in_sizes, int n_in,
                              void* d_out, int out_size)
{
    const int*   x      = (const int*)  d_in[0];
    const float* emb    = (const float*)d_in[1];
    const float* pos    = (const float*)d_in[2];
    const float* loglam = (const float*)d_in[3];
    const float* Bw     = (const float*)d_in[4];
    const float* Cw     = (const float*)d_in[5];
    const float* Dp     = (const float*)d_in[6];
    const float* n1w    = (const float*)d_in[7];
    const float* n1b    = (const float*)d_in[8];
    const float* n2w    = (const float*)d_in[9];
    const float* n2b    = (const float*)d_in[10];
    const float* w1     = (const float*)d_in[11];
    const float* w2     = (const float*)d_in[12];
    const float* w3     = (const float*)d_in[13];
    const float* now    = (const float*)d_in[14];
    const float* nob    = (const float*)d_in[15];
    const float* headW  = (const float*)d_in[16];
    const float* headb  = (const float*)d_in[17];
    float* out = (float*)d_out;

    void *ph, *pl, *pb, *pf;
    cudaGetSymbolAddress(&ph, g_h);
    cudaGetSymbolAddress(&pl, g_ln);
    cudaGetSymbolAddress(&pb, g_bu);
    cudaGetSymbolAddress(&pf, g_ff);
    float* h  = (float*)ph;
    float* ln = (float*)pl;
    float* bu = (float*)pb;
    float* ff = (float*)pf;

    k_embed<<<BT, 128>>>(x, emb, pos);

    for (int l = 0; l < Lq; l++) {
        // ---- SSM block ----
        k_ln<<<BT, 128>>>(h, ln, n1w + l * Dq, n1b + l * Dq);
        k_gemm<0><<<dim3(Sq / 128, BT / 128), 256>>>(
            ln, Bw + (size_t)l * Sq * Dq, bu, BT, Sq, Dq, nullptr, nullptr);
        k_scan1<<<32, 256>>>(loglam + l * Sq);
        k_scan2<<<2, 256>>>(loglam + l * Sq);
        k_scan3<<<32, 256>>>(loglam + l * Sq);
        k_gemm<2><<<dim3(Dq / 128, BT / 128), 256>>>(
            bu, Cw + (size_t)l * Dq * Sq, h, BT, Dq, Sq, Dp + l * Dq, ln);
        // ---- SwiGLU block ----
        k_ln<<<BT, 128>>>(h, ln, n2w + l * Dq, n2b + l * Dq);
        k_gemm<0><<<dim3((DFFq + 127) / 128, BT / 128), 256>>>(
            ln, w1 + (size_t)l * DFFq * Dq, ff, BT, DFFq, Dq, nullptr, nullptr);
        k_gemm<1><<<dim3((DFFq + 127) / 128, BT / 128), 256>>>(
            ln, w2 + (size_t)l * DFFq * Dq, ff, BT, DFFq, Dq, nullptr, nullptr);
        k_gemm<3><<<dim3(Dq / 128, BT / 128), 256>>>(
            ff, w3 + (size_t)l * Dq * DFFq, h, BT, Dq, DFFq, nullptr, nullptr);
    }

    // ---- head ----
    k_ln<<<BT, 128>>>(h, ln, now, nob);
    k_gemm<4><<<dim3(Vq / 128, BT / 128), 256>>>(
        ln, headW, out, BT, Vq, Dq, headb, nullptr);
}